// round 13
// baseline (speedup 1.0000x reference)
#include <cuda_runtime.h>
#include <cuda_fp16.h>
#include <math.h>
#include <stdint.h>

#define NN 50000
#define NE 800000
#define DIN 32
#define DD 128
#define NL 3
#define NG 64

// ---------------- edge kernel config (persistent, BM=64) ----------------
#define EBM 64
#define ETHR 128
#define EGRID 296
#define NT_E (NE/EBM)            // 12500 tiles
#define P_A 132                  // A row pitch in uints (128 kpairs + 4 pad)
#define P_H 68                   // Hs pitch
#define P_W 136                  // W stage pitch
#define WSTG (16*P_W)            // one W stage: 16 kpair rows (2 k16-steps)
#define ABUF (EBM*P_A)           // 8448 uints per A buffer
#define E_SMEM_U (2*ABUF + 2*WSTG)
#define E_SMEM_BYTES (E_SMEM_U*4)    // 84992 B -> 2 CTAs/SM

// ---------------- node kernel config (R12 proven) ----------------
#define NBM 128
#define NTHR 256
#define N_SMEM_U (NBM*P_A + 2*WSTG)
#define N_SMEM_BYTES (N_SMEM_U*4)    // 84992 B -> 2 CTAs/SM

__device__ float    g_agg[(size_t)NN * DD];
__device__ float    g_upd[(size_t)NN * DD];
__device__ int      g_counts[NG];
__device__ uint32_t g_hid16[(size_t)NN * 64];   // fp16x2 mirror of hidden
// packed half2 weights: pair (k even, k odd) along k, layout [l][k/2][n]
__device__ uint32_t g_W1h[NL * 128 * DD];
__device__ uint32_t g_W2h[NL * 64 * DD];
__device__ uint32_t g_U1h[NL * 128 * DD];
__device__ uint32_t g_U2h[NL * 64 * DD];
__device__ float    g_w1L[NL * DD];      // exact fp32 ew row (k=256)

__device__ __forceinline__ float gelu_f(float x) {
    return 0.5f * x * (1.0f + erff(x * 0.7071067811865475f));
}
__device__ __forceinline__ uint32_t f2h2(float lo, float hi) {
    uint32_t u; asm("cvt.rn.f16x2.f32 %0, %1, %2;" : "=r"(u) : "f"(hi), "f"(lo)); return u;
}

__device__ __forceinline__ void cp16cg(uint32_t* s, const uint32_t* g) {
    unsigned sa = (unsigned)__cvta_generic_to_shared(s);
    asm volatile("cp.async.cg.shared.global [%0], [%1], 16;" :: "r"(sa), "l"(g));
}
#define CP_COMMIT() asm volatile("cp.async.commit_group;")
#define CP_WAIT0()  asm volatile("cp.async.wait_group 0;")

__device__ __forceinline__ void mma16816(float* c, const uint32_t* a, const uint32_t* b) {
    asm("mma.sync.aligned.m16n8k16.row.col.f32.f16.f16.f32 "
        "{%0,%1,%2,%3}, {%4,%5,%6,%7}, {%8,%9}, {%0,%1,%2,%3};"
        : "+f"(c[0]), "+f"(c[1]), "+f"(c[2]), "+f"(c[3])
        : "r"(a[0]), "r"(a[1]), "r"(a[2]), "r"(a[3]), "r"(b[0]), "r"(b[1]));
}

__device__ __forceinline__ void red_add_v2(float* p, float a, float b) {
    asm volatile("red.global.add.v2.f32 [%0], {%1, %2};"
                 :: "l"(p), "f"(a), "f"(b) : "memory");
}
__device__ __forceinline__ void red_add_v4(float* p, float a, float b, float c, float d) {
    asm volatile("red.global.add.v4.f32 [%0], {%1, %2, %3, %4};"
                 :: "l"(p), "f"(a), "f"(b), "f"(c), "f"(d) : "memory");
}

// Pack weights to half2 (k-pairs); keep ew row exact fp32.
__global__ void prep_w(const float* __restrict__ eW1, const float* __restrict__ eW2,
                       const float* __restrict__ uW1, const float* __restrict__ uW2)
{
    int gid = blockIdx.x * blockDim.x + threadIdx.x;
    if (gid < NL * 128 * DD) {
        int l = gid / (128 * DD), rem = gid % (128 * DD), kp = rem / DD, n = rem % DD;
        g_W1h[gid] = f2h2(eW1[((size_t)l * 257 + 2 * kp) * DD + n],
                          eW1[((size_t)l * 257 + 2 * kp + 1) * DD + n]);
        g_U1h[gid] = f2h2(uW1[((size_t)l * 256 + 2 * kp) * DD + n],
                          uW1[((size_t)l * 256 + 2 * kp + 1) * DD + n]);
    }
    if (gid < NL * 64 * DD) {
        int l = gid / (64 * DD), rem = gid % (64 * DD), kp = rem / DD, n = rem % DD;
        g_W2h[gid] = f2h2(eW2[((size_t)l * DD + 2 * kp) * DD + n],
                          eW2[((size_t)l * DD + 2 * kp + 1) * DD + n]);
        g_U2h[gid] = f2h2(uW2[((size_t)l * DD + 2 * kp) * DD + n],
                          uW2[((size_t)l * DD + 2 * kp + 1) * DD + n]);
    }
    if (gid < NL * DD) {
        int l = gid / DD, n = gid % DD;
        g_w1L[gid] = eW1[((size_t)l * 257 + 256) * DD + n];
    }
}

// ======================= persistent edge kernel =======================
__global__ void __launch_bounds__(ETHR, 2) mlp_edge(
    const int* __restrict__ srcv, const int* __restrict__ dstv,
    const float* __restrict__ ew,
    const float* __restrict__ b1, const float* __restrict__ b2,
    int layer)
{
    extern __shared__ uint32_t smu[];
    uint32_t* Ab = smu;                  // [2][EBM*P_A]
    uint32_t* Wb = smu + 2 * ABUF;       // [2][WSTG]

    const int tid = threadIdx.x;
    const int warp = tid >> 5, lane = tid & 31;
    const int g = lane >> 2, tg = lane & 3;
    const int wn = warp * 32;

    const uint32_t* W1 = g_W1h + (size_t)layer * 128 * DD;
    const uint32_t* W2 = g_W2h + (size_t)layer * 64 * DD;
    const float* w1L = g_w1L + (size_t)layer * DD;

    const int srow = tid >> 3, scol = (tid & 7) << 4;   // W stage: 16 rows x 16 uints
    const int r = tid >> 1, h = tid & 1;                // gather: 2 threads/row
    const int sl = r >> 3;                              // gather slice 0..7

    float2 b1v[4], w1v[4], b2v[4];
    #pragma unroll
    for (int nt = 0; nt < 4; nt++) {
        int col = wn + nt * 8 + tg * 2;
        b1v[nt] = *(const float2*)(b1 + col);
        w1v[nt] = *(const float2*)(w1L + col);
        b2v[nt] = *(const float2*)(b2 + col);
    }

    auto gatherA = [&](uint32_t* dbuf, int s_idx, int d_idx) {
        const uint32_t* ps = g_hid16 + (size_t)s_idx * 64 + h * 32;
        const uint32_t* pd = g_hid16 + (size_t)d_idx * 64 + h * 32;
        uint32_t* arow = dbuf + r * P_A;
        #pragma unroll
        for (int j = 0; j < 8; j++) cp16cg(arow + h * 32 + j * 4, ps + j * 4);
        #pragma unroll
        for (int j = 0; j < 8; j++) cp16cg(arow + 64 + h * 32 + j * 4, pd + j * 4);
    };
    auto stage_loadW = [&](const uint32_t* Wg, int st, int buf) {
        const uint32_t* s = Wg + (size_t)(st * 16 + srow) * DD + scol;
        uint32_t* d = Wb + buf * WSTG + srow * P_W + scol;
        cp16cg(d, s); cp16cg(d + 4, s + 4); cp16cg(d + 8, s + 8); cp16cg(d + 12, s + 12);
    };

    float c[4][4][4];
    auto zero_c = [&]() {
        #pragma unroll
        for (int mt = 0; mt < 4; mt++)
            #pragma unroll
            for (int nt = 0; nt < 4; nt++) {
                c[mt][nt][0] = 0.f; c[mt][nt][1] = 0.f; c[mt][nt][2] = 0.f; c[mt][nt][3] = 0.f;
            }
    };
    auto ksteps = [&](const uint32_t* Acur, int pitch, int st, int buf) {
        #pragma unroll
        for (int j = 0; j < 2; ++j) {
            const int kt = st * 2 + j;
            uint32_t a[4][4];
            #pragma unroll
            for (int mt = 0; mt < 4; mt++) {
                const uint32_t* ap = Acur + (size_t)(mt * 16 + g) * pitch + kt * 8 + tg;
                a[mt][0] = ap[0];
                a[mt][1] = ap[8 * pitch];
                a[mt][2] = ap[4];
                a[mt][3] = ap[8 * pitch + 4];
            }
            uint32_t b[4][2];
            const uint32_t* wp = Wb + buf * WSTG + (j * 8 + tg) * P_W + wn + g;
            #pragma unroll
            for (int nt = 0; nt < 4; nt++) {
                b[nt][0] = wp[nt * 8];
                b[nt][1] = wp[nt * 8 + 4 * P_W];
            }
            #pragma unroll
            for (int mt = 0; mt < 4; mt++)
                #pragma unroll
                for (int nt = 0; nt < 4; nt++)
                    mma16816(c[mt][nt], a[mt], b[nt]);
        }
    };

    // ---------------- prologue: gather tile 0 ----------------
    int t = blockIdx.x;
    if (t >= NT_E) return;
    int s_cur = srcv[t * EBM + r], d_cur = dstv[t * EBM + r];
    gatherA(Ab, s_cur, d_cur);
    CP_COMMIT();

    int cnt = 0;
    for (; t < NT_E; t += EGRID, ++cnt) {
        const int cub = cnt & 1;
        uint32_t* Acur = Ab + cub * ABUF;
        uint32_t* Anxt = Ab + (cub ^ 1) * ABUF;
        const int tn = t + EGRID;
        const bool hasnext = tn < NT_E;
        int s_nxt = 0, d_nxt = 0;
        if (hasnext) { s_nxt = srcv[tn * EBM + r]; d_nxt = dstv[tn * EBM + r]; }

        // -------- GEMM1: 8 stages, gather slices 0..6 interleaved --------
        zero_c();
        stage_loadW(W1, 0, 0);
        CP_COMMIT();
        CP_WAIT0();          // also drains A(t) gather
        __syncthreads();
        #pragma unroll 1
        for (int st = 0; st < 8; ++st) {
            const int buf = st & 1;
            if (st < 7) {
                stage_loadW(W1, st + 1, buf ^ 1);
                if (hasnext && sl == st) gatherA(Anxt, s_nxt, d_nxt);
                CP_COMMIT();
            }
            ksteps(Acur, P_A, st, buf);
            if (st < 7) {
                CP_WAIT0();
                __syncthreads();
            }
        }
        __syncthreads();     // all warps done reading Acur before Hs overwrite

        // -------- epilogue 1: +b1 + exact ew*w1L, gelu, fp16 -> Hs (aliases Acur) --------
        #pragma unroll
        for (int mt = 0; mt < 4; mt++) {
            #pragma unroll
            for (int hh = 0; hh < 2; hh++) {
                int row = mt * 16 + g + 8 * hh;
                float ewr = ew[t * EBM + row];
                #pragma unroll
                for (int nt = 0; nt < 4; nt++) {
                    float v0 = c[mt][nt][hh * 2]     + b1v[nt].x + ewr * w1v[nt].x;
                    float v1 = c[mt][nt][hh * 2 + 1] + b1v[nt].y + ewr * w1v[nt].y;
                    int kp = (wn >> 1) + nt * 4 + tg;
                    Acur[(size_t)row * P_H + kp] = f2h2(gelu_f(v0), gelu_f(v1));
                }
            }
        }

        // -------- GEMM2: 4 stages (A = Hs), gather slice 7 at stage 0 --------
        zero_c();
        stage_loadW(W2, 0, 0);
        if (hasnext && sl == 7) gatherA(Anxt, s_nxt, d_nxt);
        CP_COMMIT();
        CP_WAIT0();
        __syncthreads();     // publishes Hs writes for all warps
        #pragma unroll 1
        for (int st = 0; st < 4; ++st) {
            const int buf = st & 1;
            if (st < 3) {
                stage_loadW(W2, st + 1, buf ^ 1);
                CP_COMMIT();
            }
            ksteps(Acur, P_H, st, buf);
            if (st < 3) {
                CP_WAIT0();
                __syncthreads();
            }
        }

        // -------- epilogue 2: +b2, red.v2 scatter --------
        #pragma unroll
        for (int mt = 0; mt < 4; mt++) {
            #pragma unroll
            for (int hh = 0; hh < 2; hh++) {
                int row = mt * 16 + g + 8 * hh;
                float* base = g_agg + (size_t)dstv[t * EBM + row] * DD;
                #pragma unroll
                for (int nt = 0; nt < 4; nt++) {
                    int col = wn + nt * 8 + tg * 2;
                    red_add_v2(base + col,
                               c[mt][nt][hh * 2] + b2v[nt].x,
                               c[mt][nt][hh * 2 + 1] + b2v[nt].y);
                }
            }
        }
        s_cur = s_nxt; d_cur = d_nxt;
    }
}

// ======================= node kernel (R12 proven) =======================
__global__ void __launch_bounds__(NTHR, 2) mlp_node(
    const float* __restrict__ hidden,
    const float* __restrict__ b1, const float* __restrict__ b2,
    int layer, int M)
{
    extern __shared__ uint32_t smu[];
    uint32_t* A16 = smu;
    uint32_t* Wb  = smu + NBM * P_A;

    const int tid = threadIdx.x;
    const int warp = tid >> 5, lane = tid & 31;
    const int g = lane >> 2, tg = lane & 3;
    const int wm = (warp >> 2) * 64;
    const int wn = (warp & 3) * 32;
    const int m0 = blockIdx.x * NBM;

    const uint32_t* W1 = g_U1h + (size_t)layer * 128 * DD;
    const uint32_t* W2 = g_U2h + (size_t)layer * 64 * DD;

    const int srow = tid >> 4, scol = (tid & 15) << 3;

    {
        const int r = tid >> 1, h = tid & 1;
        int row = m0 + r;
        if (row >= M) row = M - 1;
        const uint32_t* p0 = g_hid16 + (size_t)row * 64 + h * 32;
        const float* p1 = g_agg + (size_t)row * DD + h * 64;
        uint32_t* arow = A16 + r * P_A;
        #pragma unroll
        for (int i = 0; i < 8; i++)
            *(uint4*)&arow[h * 32 + i * 4] = ((const uint4*)p0)[i];
        #pragma unroll
        for (int i = 0; i < 16; i++) {
            float4 v = ((const float4*)p1)[i];
            *(uint2*)&arow[64 + h * 32 + i * 2] = make_uint2(f2h2(v.x, v.y), f2h2(v.z, v.w));
        }
    }

    float c[4][4][4];

    auto run_gemm = [&](const uint32_t* Wg, int nstages, const uint32_t* Ab, int pitch) {
        #pragma unroll
        for (int mt = 0; mt < 4; mt++)
            #pragma unroll
            for (int nt = 0; nt < 4; nt++) {
                c[mt][nt][0] = 0.f; c[mt][nt][1] = 0.f; c[mt][nt][2] = 0.f; c[mt][nt][3] = 0.f;
            }
        auto stage_load = [&](int st, int buf) {
            const uint32_t* s = Wg + (size_t)(st * 16 + srow) * DD + scol;
            uint32_t* d = Wb + buf * WSTG + srow * P_W + scol;
            cp16cg(d, s); cp16cg(d + 4, s + 4);
            CP_COMMIT();
        };
        stage_load(0, 0);
        CP_WAIT0();
        __syncthreads();
        #pragma unroll 1
        for (int st = 0; st < nstages; ++st) {
            const int buf = st & 1;
            if (st + 1 < nstages) stage_load(st + 1, buf ^ 1);
            #pragma unroll
            for (int j = 0; j < 2; ++j) {
                const int kt = st * 2 + j;
                uint32_t a[4][4];
                #pragma unroll
                for (int mt = 0; mt < 4; mt++) {
                    const uint32_t* ap = Ab + (size_t)(wm + mt * 16 + g) * pitch + kt * 8 + tg;
                    a[mt][0] = ap[0];
                    a[mt][1] = ap[8 * pitch];
                    a[mt][2] = ap[4];
                    a[mt][3] = ap[8 * pitch + 4];
                }
                uint32_t b[4][2];
                const uint32_t* wp = Wb + buf * WSTG + (j * 8 + tg) * P_W + wn + g;
                #pragma unroll
                for (int nt = 0; nt < 4; nt++) {
                    b[nt][0] = wp[nt * 8];
                    b[nt][1] = wp[nt * 8 + 4 * P_W];
                }
                #pragma unroll
                for (int mt = 0; mt < 4; mt++)
                    #pragma unroll
                    for (int nt = 0; nt < 4; nt++)
                        mma16816(c[mt][nt], a[mt], b[nt]);
            }
            if (st + 1 < nstages) {
                CP_WAIT0();
                __syncthreads();
            }
        }
    };

    run_gemm(W1, 8, A16, P_A);
    __syncthreads();

    {
        float2 b1v[4];
        #pragma unroll
        for (int nt = 0; nt < 4; nt++)
            b1v[nt] = *(const float2*)(b1 + wn + nt * 8 + tg * 2);
        #pragma unroll
        for (int mt = 0; mt < 4; mt++) {
            #pragma unroll
            for (int hh = 0; hh < 2; hh++) {
                int row = wm + mt * 16 + g + 8 * hh;
                #pragma unroll
                for (int nt = 0; nt < 4; nt++) {
                    float v0 = c[mt][nt][hh * 2]     + b1v[nt].x;
                    float v1 = c[mt][nt][hh * 2 + 1] + b1v[nt].y;
                    int kp = (wn >> 1) + nt * 4 + tg;
                    A16[(size_t)row * P_H + kp] = f2h2(gelu_f(v0), gelu_f(v1));
                }
            }
        }
    }

    run_gemm(W2, 4, A16, P_H);

    {
        float2 b2v[4];
        #pragma unroll
        for (int nt = 0; nt < 4; nt++)
            b2v[nt] = *(const float2*)(b2 + wn + nt * 8 + tg * 2);
        #pragma unroll
        for (int mt = 0; mt < 4; mt++) {
            #pragma unroll
            for (int hh = 0; hh < 2; hh++) {
                int row = wm + mt * 16 + g + 8 * hh;
                if (m0 + row < M) {
                    float* base = g_upd + (size_t)(m0 + row) * DD;
                    #pragma unroll
                    for (int nt = 0; nt < 4; nt++) {
                        int col = wn + nt * 8 + tg * 2;
                        *(float2*)(base + col) = make_float2(
                            c[mt][nt][hh * 2] + b2v[nt].x,
                            c[mt][nt][hh * 2 + 1] + b2v[nt].y);
                    }
                }
            }
        }
    }
}

__global__ void input_proj_kernel(const float* __restrict__ x, const float* __restrict__ W,
                                  const float* __restrict__ b, float* __restrict__ hidden)
{
    int gid = blockIdx.x * blockDim.x + threadIdx.x;
    if (gid >= NN * 32) return;
    int node = gid >> 5;
    int c4 = (gid & 31) << 2;
    const float* xr = x + (size_t)node * DIN;
    float4 acc = *(const float4*)(b + c4);
    #pragma unroll
    for (int k = 0; k < DIN; k++) {
        float xv = xr[k];
        float4 w = *(const float4*)(W + (size_t)k * DD + c4);
        acc.x += xv * w.x; acc.y += xv * w.y; acc.z += xv * w.z; acc.w += xv * w.w;
    }
    float4 o = make_float4(gelu_f(acc.x), gelu_f(acc.y), gelu_f(acc.z), gelu_f(acc.w));
    *(float4*)(hidden + (size_t)node * DD + c4) = o;
    *(uint2*)(g_hid16 + (size_t)node * 64 + (c4 >> 1)) =
        make_uint2(f2h2(o.x, o.y), f2h2(o.z, o.w));
}

__global__ void ln_kernel(float* __restrict__ hidden, const float* __restrict__ gamma,
                          const float* __restrict__ beta)
{
    int gw = (blockIdx.x * blockDim.x + threadIdx.x) >> 5;
    if (gw >= NN) return;
    int lane = threadIdx.x & 31;
    float4 h = ((const float4*)(hidden + (size_t)gw * DD))[lane];
    float4 u = ((const float4*)(g_upd + (size_t)gw * DD))[lane];
    float x0 = h.x + u.x, x1 = h.y + u.y, x2 = h.z + u.z, x3 = h.w + u.w;
    float s = x0 + x1 + x2 + x3;
    #pragma unroll
    for (int o = 16; o > 0; o >>= 1) s += __shfl_xor_sync(0xffffffffu, s, o);
    float mu = s * (1.0f / 128.0f);
    float d0 = x0 - mu, d1 = x1 - mu, d2 = x2 - mu, d3 = x3 - mu;
    float v = d0 * d0 + d1 * d1 + d2 * d2 + d3 * d3;
    #pragma unroll
    for (int o = 16; o > 0; o >>= 1) v += __shfl_xor_sync(0xffffffffu, v, o);
    float r = rsqrtf(v * (1.0f / 128.0f) + 1e-5f);
    float4 gm = ((const float4*)gamma)[lane];
    float4 bb = ((const float4*)beta)[lane];
    float4 o4 = make_float4(d0 * r * gm.x + bb.x, d1 * r * gm.y + bb.y,
                            d2 * r * gm.z + bb.z, d3 * r * gm.w + bb.w);
    ((float4*)(hidden + (size_t)gw * DD))[lane] = o4;
    *(uint2*)(g_hid16 + (size_t)gw * 64 + lane * 2) =
        make_uint2(f2h2(o4.x, o4.y), f2h2(o4.z, o4.w));
}

__global__ void zero_agg_kernel()
{
    int gid = blockIdx.x * blockDim.x + threadIdx.x;
    if (gid < NN * DD / 4) ((float4*)g_agg)[gid] = make_float4(0.f, 0.f, 0.f, 0.f);
}

__global__ void zero_pool_kernel(float* __restrict__ out)
{
    int gid = blockIdx.x * blockDim.x + threadIdx.x;
    if (gid < NG * DD) out[(size_t)NN * DD + gid] = 0.f;
    if (gid < NG) g_counts[gid] = 0;
}

__global__ void pool_accum_kernel(const float* __restrict__ hidden, const int* __restrict__ batch,
                                  float* __restrict__ out)
{
    int gid = blockIdx.x * blockDim.x + threadIdx.x;
    if (gid >= NN * 32) return;
    int node = gid >> 5;
    int c4 = (gid & 31) << 2;
    int g = batch[node];
    float4 h = *(const float4*)(hidden + (size_t)node * DD + c4);
    float* base = out + (size_t)NN * DD + (size_t)g * DD + c4;
    red_add_v4(base, h.x, h.y, h.z, h.w);
    if ((gid & 31) == 0) atomicAdd(&g_counts[g], 1);
}

__global__ void pool_div_kernel(float* __restrict__ out)
{
    int gid = blockIdx.x * blockDim.x + threadIdx.x;
    if (gid >= NG * DD) return;
    int g = gid >> 7;
    int cnt = g_counts[g];
    float cden = (float)(cnt > 1 ? cnt : 1);
    out[(size_t)NN * DD + gid] /= cden;
}

extern "C" void kernel_launch(void* const* d_in, const int* in_sizes, int n_in,
                              void* d_out, int out_size)
{
    const float* node_features = (const float*)d_in[0];
    const int*   edge_index    = (const int*)d_in[1];
    const float* edge_weight   = (const float*)d_in[2];
    const int*   batch_index   = (const int*)d_in[3];
    const float* W_in  = (const float*)d_in[5];
    const float* b_in  = (const float*)d_in[6];
    const float* eW1   = (const float*)d_in[7];
    const float* eb1   = (const float*)d_in[8];
    const float* eW2   = (const float*)d_in[9];
    const float* eb2   = (const float*)d_in[10];
    const float* uW1   = (const float*)d_in[11];
    const float* ub1   = (const float*)d_in[12];
    const float* uW2   = (const float*)d_in[13];
    const float* ub2   = (const float*)d_in[14];
    const float* gamma = (const float*)d_in[15];
    const float* beta  = (const float*)d_in[16];
    float* out = (float*)d_out;

    const int* src = edge_index;
    const int* dst = edge_index + NE;

    cudaFuncSetAttribute(mlp_edge, cudaFuncAttributeMaxDynamicSharedMemorySize, E_SMEM_BYTES);
    cudaFuncSetAttribute(mlp_node, cudaFuncAttributeMaxDynamicSharedMemorySize, N_SMEM_BYTES);

    prep_w<<<(NL * 128 * DD + 255) / 256, 256>>>(eW1, eW2, uW1, uW2);
    zero_pool_kernel<<<(NG * DD + 255) / 256, 256>>>(out);
    input_proj_kernel<<<(NN * 32 + 255) / 256, 256>>>(node_features, W_in, b_in, out);

    for (int l = 0; l < NL; ++l) {
        zero_agg_kernel<<<(NN * DD / 4 + 255) / 256, 256>>>();
        mlp_edge<<<EGRID, ETHR, E_SMEM_BYTES>>>(
            src, dst, edge_weight,
            eb1 + (size_t)l * DD, eb2 + (size_t)l * DD, l);
        mlp_node<<<(NN + NBM - 1) / NBM, NTHR, N_SMEM_BYTES>>>(
            out, ub1 + (size_t)l * DD, ub2 + (size_t)l * DD, l, NN);
        ln_kernel<<<(NN * 32 + 255) / 256, 256>>>(out, gamma + (size_t)l * DD, beta + (size_t)l * DD);
    }

    pool_accum_kernel<<<(NN * 32 + 255) / 256, 256>>>(out, batch_index, out);
    pool_div_kernel<<<(NG * DD + 255) / 256, 256>>>(out);
}

// round 14
// speedup vs baseline: 1.0915x; 1.0915x over previous
#include <cuda_runtime.h>
#include <cuda_fp16.h>
#include <math.h>
#include <stdint.h>

#define NN 50000
#define NE 800000
#define DIN 32
#define DD 128
#define NL 3
#define NG 64

#define BM 128
#define NTHR 256
#define P_A 132                  // A16 pitch (uints)
#define P_H 68                   // Hs pitch (uints)
#define P_W 136                  // W stage pitch (uints)
#define WSTG (16*P_W)            // uints per W stage (16 kpair rows = 2 k16-steps)
#define SMEM_U (BM*P_A + 2*WSTG)
#define SMEM_BYTES (SMEM_U*4)    // 84992 B -> 2 CTAs/SM

__device__ uint32_t g_agg16[(size_t)NN * 64];   // fp16x2 aggregate
__device__ float    g_upd[(size_t)NN * DD];
__device__ int      g_counts[NG];
// packed half2 weights: pair (k even, k odd) along k, layout [l][k/2][n]
__device__ uint32_t g_W1h[NL * 128 * DD];
__device__ uint32_t g_W2h[NL * 64 * DD];
__device__ uint32_t g_U1h[NL * 128 * DD];
__device__ uint32_t g_U2h[NL * 64 * DD];
__device__ float    g_w1L[NL * DD];      // exact fp32 ew row (k=256)

__device__ __forceinline__ float gelu_f(float x) {
    return 0.5f * x * (1.0f + erff(x * 0.7071067811865475f));
}
__device__ __forceinline__ uint32_t f2h2(float lo, float hi) {
    uint32_t u; asm("cvt.rn.f16x2.f32 %0, %1, %2;" : "=r"(u) : "f"(hi), "f"(lo)); return u;
}

__device__ __forceinline__ void cp16cg(uint32_t* s, const uint32_t* g) {
    unsigned sa = (unsigned)__cvta_generic_to_shared(s);
    asm volatile("cp.async.cg.shared.global [%0], [%1], 16;" :: "r"(sa), "l"(g));
}
#define CP_COMMIT() asm volatile("cp.async.commit_group;")
#define CP_WAIT0()  asm volatile("cp.async.wait_group 0;")

__device__ __forceinline__ void mma16816(float* c, const uint32_t* a, const uint32_t* b) {
    asm("mma.sync.aligned.m16n8k16.row.col.f32.f16.f16.f32 "
        "{%0,%1,%2,%3}, {%4,%5,%6,%7}, {%8,%9}, {%0,%1,%2,%3};"
        : "+f"(c[0]), "+f"(c[1]), "+f"(c[2]), "+f"(c[3])
        : "r"(a[0]), "r"(a[1]), "r"(a[2]), "r"(a[3]), "r"(b[0]), "r"(b[1]));
}

__device__ __forceinline__ void red4h(uint32_t* p, uint4 v) {
    asm volatile("red.global.add.noftz.v4.f16x2 [%0], {%1,%2,%3,%4};"
                 :: "l"(p), "r"(v.x), "r"(v.y), "r"(v.z), "r"(v.w) : "memory");
}
__device__ __forceinline__ void red_add_v4(float* p, float a, float b, float c, float d) {
    asm volatile("red.global.add.v4.f32 [%0], {%1, %2, %3, %4};"
                 :: "l"(p), "f"(a), "f"(b), "f"(c), "f"(d) : "memory");
}

// Pack weights to half2 (k-pairs); keep ew row exact fp32.
__global__ void prep_w(const float* __restrict__ eW1, const float* __restrict__ eW2,
                       const float* __restrict__ uW1, const float* __restrict__ uW2)
{
    int gid = blockIdx.x * blockDim.x + threadIdx.x;
    if (gid < NL * 128 * DD) {
        int l = gid / (128 * DD), rem = gid % (128 * DD), kp = rem / DD, n = rem % DD;
        g_W1h[gid] = f2h2(eW1[((size_t)l * 257 + 2 * kp) * DD + n],
                          eW1[((size_t)l * 257 + 2 * kp + 1) * DD + n]);
        g_U1h[gid] = f2h2(uW1[((size_t)l * 256 + 2 * kp) * DD + n],
                          uW1[((size_t)l * 256 + 2 * kp + 1) * DD + n]);
    }
    if (gid < NL * 64 * DD) {
        int l = gid / (64 * DD), rem = gid % (64 * DD), kp = rem / DD, n = rem % DD;
        g_W2h[gid] = f2h2(eW2[((size_t)l * DD + 2 * kp) * DD + n],
                          eW2[((size_t)l * DD + 2 * kp + 1) * DD + n]);
        g_U2h[gid] = f2h2(uW2[((size_t)l * DD + 2 * kp) * DD + n],
                          uW2[((size_t)l * DD + 2 * kp + 1) * DD + n]);
    }
    if (gid < NL * DD) {
        int l = gid / DD, n = gid % DD;
        g_w1L[gid] = eW1[((size_t)l * 257 + 256) * DD + n];
    }
}

// MODE 0: edge MLP: gather fp32->fp16 [h_src|h_dst] -> f16 mma x2 (+exact ew rank-1)
//         -> vectorized f16x2 red scatter to g_agg16
// MODE 1: node MLP: [hidden(fp16 cvt) | g_agg16 raw] -> f16 mma x2 -> store g_upd (fp32)
template<int MODE>
__global__ void __launch_bounds__(NTHR, 2) mlp_mma(
    const float* __restrict__ hidden,
    const int* __restrict__ srcv, const int* __restrict__ dstv,
    const float* __restrict__ ew,
    const float* __restrict__ b1, const float* __restrict__ b2,
    int layer, int M)
{
    extern __shared__ uint32_t smu[];
    uint32_t* A16 = smu;             // [BM][P_A] kpairs; Hs ([BM][P_H]) aliases after GEMM1
    uint32_t* Wb  = smu + BM * P_A;  // [2][16][P_W]

    const int tid = threadIdx.x;
    const int warp = tid >> 5, lane = tid & 31;
    const int g = lane >> 2, tg = lane & 3;
    const int wm = (warp >> 2) * 64;     // warp m base (0 or 64)
    const int wn = (warp & 3) * 32;      // warp n base
    const int m0 = blockIdx.x * BM;

    const uint32_t* W1 = (MODE == 0 ? g_W1h : g_U1h) + (size_t)layer * 128 * DD;
    const uint32_t* W2 = (MODE == 0 ? g_W2h : g_U2h) + (size_t)layer * 64 * DD;
    const float* w1L = g_w1L + (size_t)layer * DD;

    // W stage load geometry: 256 thr -> 16 rows x (16 thr x 8 uints)
    const int srow = tid >> 4, scol = (tid & 15) << 3;

    // ---------------- gather A tile ----------------
    {
        const int r = tid >> 1, h = tid & 1;     // r: 0..127
        int row = m0 + r;
        uint32_t* arow = A16 + r * P_A;
        if (MODE == 0) {
            const float* p0 = hidden + (size_t)srcv[row] * DD + h * 64;
            const float* p1 = hidden + (size_t)dstv[row] * DD + h * 64;
            #pragma unroll
            for (int i = 0; i < 16; i++) {
                float4 v = ((const float4*)p0)[i];
                *(uint2*)&arow[h * 32 + i * 2] = make_uint2(f2h2(v.x, v.y), f2h2(v.z, v.w));
            }
            #pragma unroll
            for (int i = 0; i < 16; i++) {
                float4 v = ((const float4*)p1)[i];
                *(uint2*)&arow[64 + h * 32 + i * 2] = make_uint2(f2h2(v.x, v.y), f2h2(v.z, v.w));
            }
        } else {
            if (row >= M) row = M - 1;
            const float* p0 = hidden + (size_t)row * DD + h * 64;
            const uint32_t* p1 = g_agg16 + (size_t)row * 64 + h * 32;
            #pragma unroll
            for (int i = 0; i < 16; i++) {
                float4 v = ((const float4*)p0)[i];
                *(uint2*)&arow[h * 32 + i * 2] = make_uint2(f2h2(v.x, v.y), f2h2(v.z, v.w));
            }
            #pragma unroll
            for (int i = 0; i < 8; i++)
                *(uint4*)&arow[64 + h * 32 + i * 4] = ((const uint4*)p1)[i];
        }
    }

    float c[4][4][4];   // [m-tile][n-tile][frag]

    auto run_gemm = [&](const uint32_t* Wg, int nstages, const uint32_t* Ab, int pitch) {
        #pragma unroll
        for (int mt = 0; mt < 4; mt++)
            #pragma unroll
            for (int nt = 0; nt < 4; nt++) {
                c[mt][nt][0] = 0.f; c[mt][nt][1] = 0.f; c[mt][nt][2] = 0.f; c[mt][nt][3] = 0.f;
            }
        auto stage_load = [&](int st, int buf) {
            const uint32_t* s = Wg + (size_t)(st * 16 + srow) * DD + scol;
            uint32_t* d = Wb + buf * WSTG + srow * P_W + scol;
            cp16cg(d, s); cp16cg(d + 4, s + 4);
            CP_COMMIT();
        };
        stage_load(0, 0);
        CP_WAIT0();
        __syncthreads();
        #pragma unroll 1
        for (int st = 0; st < nstages; ++st) {
            const int buf = st & 1;
            if (st + 1 < nstages) stage_load(st + 1, buf ^ 1);
            #pragma unroll
            for (int j = 0; j < 2; ++j) {
                const int kt = st * 2 + j;
                uint32_t a[4][4];
                #pragma unroll
                for (int mt = 0; mt < 4; mt++) {
                    const uint32_t* ap = Ab + (size_t)(wm + mt * 16 + g) * pitch + kt * 8 + tg;
                    a[mt][0] = ap[0];
                    a[mt][1] = ap[8 * pitch];
                    a[mt][2] = ap[4];
                    a[mt][3] = ap[8 * pitch + 4];
                }
                uint32_t b[4][2];
                const uint32_t* wp = Wb + buf * WSTG + (j * 8 + tg) * P_W + wn + g;
                #pragma unroll
                for (int nt = 0; nt < 4; nt++) {
                    b[nt][0] = wp[nt * 8];
                    b[nt][1] = wp[nt * 8 + 4 * P_W];
                }
                #pragma unroll
                for (int mt = 0; mt < 4; mt++)
                    #pragma unroll
                    for (int nt = 0; nt < 4; nt++)
                        mma16816(c[mt][nt], a[mt], b[nt]);
            }
            if (st + 1 < nstages) {
                CP_WAIT0();
                __syncthreads();
            }
        }
    };

    // ---------------- GEMM1: A[BM,256] x W1[256,128] (8 stages) ----------------
    run_gemm(W1, 8, A16, P_A);
    __syncthreads();   // all warps done reading A16 before Hs overwrite

    // ---------------- epilogue 1: +b1 (+ew*w1L exact), gelu, fp16 -> Hs ----------------
    {
        float2 b1v[4], w1v[4];
        #pragma unroll
        for (int nt = 0; nt < 4; nt++) {
            int col = wn + nt * 8 + tg * 2;
            b1v[nt] = *(const float2*)(b1 + col);
            if (MODE == 0) w1v[nt] = *(const float2*)(w1L + col);
        }
        #pragma unroll
        for (int mt = 0; mt < 4; mt++) {
            #pragma unroll
            for (int hh = 0; hh < 2; hh++) {
                int row = wm + mt * 16 + g + 8 * hh;
                float ewr = 0.f;
                if (MODE == 0) ewr = ew[m0 + row];
                #pragma unroll
                for (int nt = 0; nt < 4; nt++) {
                    float v0 = c[mt][nt][hh * 2]     + b1v[nt].x;
                    float v1 = c[mt][nt][hh * 2 + 1] + b1v[nt].y;
                    if (MODE == 0) { v0 += ewr * w1v[nt].x; v1 += ewr * w1v[nt].y; }
                    int kp = (wn >> 1) + nt * 4 + tg;
                    A16[(size_t)row * P_H + kp] = f2h2(gelu_f(v0), gelu_f(v1));
                }
            }
        }
    }
    // gemm2's internal barrier (after stage-0 wait) publishes the Hs writes.

    // ---------------- GEMM2: Hs[BM,128] x W2[128,128] (4 stages) ----------------
    run_gemm(W2, 4, A16, P_H);

    // ---------------- epilogue 2 ----------------
    {
        float2 b2v[4];
        #pragma unroll
        for (int nt = 0; nt < 4; nt++)
            b2v[nt] = *(const float2*)(b2 + wn + nt * 8 + tg * 2);
        if (MODE == 0) {
            // stash C as f16x2 into the dead Hs region, then vectorized row scatter
            __syncthreads();
            #pragma unroll
            for (int mt = 0; mt < 4; mt++) {
                #pragma unroll
                for (int hh = 0; hh < 2; hh++) {
                    int row = wm + mt * 16 + g + 8 * hh;
                    #pragma unroll
                    for (int nt = 0; nt < 4; nt++) {
                        float v0 = c[mt][nt][hh * 2]     + b2v[nt].x;
                        float v1 = c[mt][nt][hh * 2 + 1] + b2v[nt].y;
                        int kp = (wn >> 1) + nt * 4 + tg;
                        A16[(size_t)row * P_H + kp] = f2h2(v0, v1);
                    }
                }
            }
            __syncthreads();
            const int r = tid >> 1, h = tid & 1;
            uint32_t* base = g_agg16 + (size_t)dstv[m0 + r] * 64 + h * 32;
            const uint32_t* arow = A16 + r * P_H + h * 32;
            #pragma unroll
            for (int j = 0; j < 8; j++) {
                uint4 v = *(const uint4*)&arow[j * 4];
                red4h(base + j * 4, v);
            }
        } else {
            #pragma unroll
            for (int mt = 0; mt < 4; mt++) {
                #pragma unroll
                for (int hh = 0; hh < 2; hh++) {
                    int row = wm + mt * 16 + g + 8 * hh;
                    if (m0 + row < M) {
                        float* base = g_upd + (size_t)(m0 + row) * DD;
                        #pragma unroll
                        for (int nt = 0; nt < 4; nt++) {
                            int col = wn + nt * 8 + tg * 2;
                            *(float2*)(base + col) = make_float2(
                                c[mt][nt][hh * 2] + b2v[nt].x,
                                c[mt][nt][hh * 2 + 1] + b2v[nt].y);
                        }
                    }
                }
            }
        }
    }
}

__global__ void input_proj_kernel(const float* __restrict__ x, const float* __restrict__ W,
                                  const float* __restrict__ b, float* __restrict__ hidden)
{
    int gid = blockIdx.x * blockDim.x + threadIdx.x;
    if (gid >= NN * 32) return;
    int node = gid >> 5;
    int c4 = (gid & 31) << 2;
    const float* xr = x + (size_t)node * DIN;
    float4 acc = *(const float4*)(b + c4);
    #pragma unroll
    for (int k = 0; k < DIN; k++) {
        float xv = xr[k];
        float4 w = *(const float4*)(W + (size_t)k * DD + c4);
        acc.x += xv * w.x; acc.y += xv * w.y; acc.z += xv * w.z; acc.w += xv * w.w;
    }
    float4 o = make_float4(gelu_f(acc.x), gelu_f(acc.y), gelu_f(acc.z), gelu_f(acc.w));
    *(float4*)(hidden + (size_t)node * DD + c4) = o;
}

__global__ void ln_kernel(float* __restrict__ hidden, const float* __restrict__ gamma,
                          const float* __restrict__ beta)
{
    int gw = (blockIdx.x * blockDim.x + threadIdx.x) >> 5;
    if (gw >= NN) return;
    int lane = threadIdx.x & 31;
    float4 h = ((const float4*)(hidden + (size_t)gw * DD))[lane];
    float4 u = ((const float4*)(g_upd + (size_t)gw * DD))[lane];
    float x0 = h.x + u.x, x1 = h.y + u.y, x2 = h.z + u.z, x3 = h.w + u.w;
    float s = x0 + x1 + x2 + x3;
    #pragma unroll
    for (int o = 16; o > 0; o >>= 1) s += __shfl_xor_sync(0xffffffffu, s, o);
    float mu = s * (1.0f / 128.0f);
    float d0 = x0 - mu, d1 = x1 - mu, d2 = x2 - mu, d3 = x3 - mu;
    float v = d0 * d0 + d1 * d1 + d2 * d2 + d3 * d3;
    #pragma unroll
    for (int o = 16; o > 0; o >>= 1) v += __shfl_xor_sync(0xffffffffu, v, o);
    float r = rsqrtf(v * (1.0f / 128.0f) + 1e-5f);
    float4 gm = ((const float4*)gamma)[lane];
    float4 bb = ((const float4*)beta)[lane];
    float4 o4 = make_float4(d0 * r * gm.x + bb.x, d1 * r * gm.y + bb.y,
                            d2 * r * gm.z + bb.z, d3 * r * gm.w + bb.w);
    ((float4*)(hidden + (size_t)gw * DD))[lane] = o4;
}

__global__ void zero_agg_kernel()
{
    int gid = blockIdx.x * blockDim.x + threadIdx.x;
    if (gid < NN * 16) ((uint4*)g_agg16)[gid] = make_uint4(0, 0, 0, 0);
}

// zeroes pooled output, counts, AND layer-0 g_agg16
__global__ void zero_pool_kernel(float* __restrict__ out)
{
    int gid = blockIdx.x * blockDim.x + threadIdx.x;
    if (gid < NG * DD) out[(size_t)NN * DD + gid] = 0.f;
    if (gid < NG) g_counts[gid] = 0;
    if (gid < NN * 16) ((uint4*)g_agg16)[gid] = make_uint4(0, 0, 0, 0);
}

__global__ void pool_accum_kernel(const float* __restrict__ hidden, const int* __restrict__ batch,
                                  float* __restrict__ out)
{
    int gid = blockIdx.x * blockDim.x + threadIdx.x;
    if (gid >= NN * 32) return;
    int node = gid >> 5;
    int c4 = (gid & 31) << 2;
    int g = batch[node];
    float4 h = *(const float4*)(hidden + (size_t)node * DD + c4);
    float* base = out + (size_t)NN * DD + (size_t)g * DD + c4;
    red_add_v4(base, h.x, h.y, h.z, h.w);
    if ((gid & 31) == 0) atomicAdd(&g_counts[g], 1);
}

__global__ void pool_div_kernel(float* __restrict__ out)
{
    int gid = blockIdx.x * blockDim.x + threadIdx.x;
    if (gid >= NG * DD) return;
    int g = gid >> 7;
    int cnt = g_counts[g];
    float cden = (float)(cnt > 1 ? cnt : 1);
    out[(size_t)NN * DD + gid] /= cden;
}

extern "C" void kernel_launch(void* const* d_in, const int* in_sizes, int n_in,
                              void* d_out, int out_size)
{
    const float* node_features = (const float*)d_in[0];
    const int*   edge_index    = (const int*)d_in[1];
    const float* edge_weight   = (const float*)d_in[2];
    const int*   batch_index   = (const int*)d_in[3];
    const float* W_in  = (const float*)d_in[5];
    const float* b_in  = (const float*)d_in[6];
    const float* eW1   = (const float*)d_in[7];
    const float* eb1   = (const float*)d_in[8];
    const float* eW2   = (const float*)d_in[9];
    const float* eb2   = (const float*)d_in[10];
    const float* uW1   = (const float*)d_in[11];
    const float* ub1   = (const float*)d_in[12];
    const float* uW2   = (const float*)d_in[13];
    const float* ub2   = (const float*)d_in[14];
    const float* gamma = (const float*)d_in[15];
    const float* beta  = (const float*)d_in[16];
    float* out = (float*)d_out;

    const int* src = edge_index;
    const int* dst = edge_index + NE;

    cudaFuncSetAttribute(mlp_mma<0>, cudaFuncAttributeMaxDynamicSharedMemorySize, SMEM_BYTES);
    cudaFuncSetAttribute(mlp_mma<1>, cudaFuncAttributeMaxDynamicSharedMemorySize, SMEM_BYTES);

    // launch order puts the layer-0 edge kernel at profiled slot 4
    prep_w<<<(NL * 128 * DD + 255) / 256, 256>>>(eW1, eW2, uW1, uW2);
    zero_pool_kernel<<<(NN * 16 + 255) / 256, 256>>>(out);
    input_proj_kernel<<<(NN * 32 + 255) / 256, 256>>>(node_features, W_in, b_in, out);

    for (int l = 0; l < NL; ++l) {
        if (l > 0)
            zero_agg_kernel<<<(NN * 16 + 255) / 256, 256>>>();
        mlp_mma<0><<<NE / BM, NTHR, SMEM_BYTES>>>(
            out, src, dst, edge_weight,
            eb1 + (size_t)l * DD, eb2 + (size_t)l * DD, l, NE);
        mlp_mma<1><<<(NN + BM - 1) / BM, NTHR, SMEM_BYTES>>>(
            out, (const int*)0, (const int*)0, (const float*)0,
            ub1 + (size_t)l * DD, ub2 + (size_t)l * DD, l, NN);
        ln_kernel<<<(NN * 32 + 255) / 256, 256>>>(out, gamma + (size_t)l * DD, beta + (size_t)l * DD);
    }

    pool_accum_kernel<<<(NN * 32 + 255) / 256, 256>>>(out, batch_index, out);
    pool_div_kernel<<<(NG * DD + 255) / 256, 256>>>(out);
}